// round 12
// baseline (speedup 1.0000x reference)
#include <cuda_runtime.h>

#define B_  4
#define L_  1024
#define D_  512
#define H_  8
#define DK_ 64

// ---------------- scratch (no allocations allowed) ----------------
__device__ float g_Q [B_*L_*D_];
__device__ float g_K [B_*L_*D_];
__device__ float g_V [B_*L_*D_];
__device__ float g_QP[B_*L_*D_];
__device__ float g_KP[B_*L_*D_];
__device__ float g_AV[B_*L_*D_];
__device__ float g_g [B_*L_];

// ---------------- packed f32x2 helpers (FFMA2) ----------------
typedef unsigned long long u64;

__device__ __forceinline__ u64 pk2(float lo, float hi) {
    u64 r;
    asm("mov.b64 %0, {%1, %2};" : "=l"(r) : "f"(lo), "f"(hi));
    return r;
}
__device__ __forceinline__ void ffma2(u64& d, u64 a, u64 b) {
    asm("fma.rn.f32x2 %0, %1, %2, %0;" : "+l"(d) : "l"(a), "l"(b));
}
__device__ __forceinline__ float2 upk(u64 v) {
    float2 f;
    asm("mov.b64 {%0, %1}, %2;" : "=f"(f.x), "=f"(f.y) : "l"(v));
    return f;
}

// =================================================================
// Core NN SGEMM tile: C[M,N] = A[M,512] @ W[512,N] + bias
// 128x128 tile, BK=16, 256 threads, 8x8 micro-tile, FFMA2 (m-paired).
// =================================================================
__device__ __forceinline__ void gemm_nn_core(
    const float* __restrict__ A, const float* __restrict__ W,
    const float* __restrict__ bias, float* __restrict__ C,
    float As[16][132], float Ws[16][132])
{
    const int tid = threadIdx.x;
    const int tx = tid & 15;          // n micro-group
    const int ty = tid >> 4;          // m micro-group
    const int m0 = blockIdx.y * 128, n0 = blockIdx.x * 128;

    u64 acc2[4][8] = {};              // [m-pair][n]

    for (int k0 = 0; k0 < 512; k0 += 16) {
        #pragma unroll
        for (int l = 0; l < 2; l++) {
            int idx = tid + l * 256;
            int r = idx & 127;
            int c = (idx >> 7) * 4;
            float4 v = *(const float4*)(A + (size_t)(m0 + r) * 512 + k0 + c);
            As[c+0][r] = v.x; As[c+1][r] = v.y;
            As[c+2][r] = v.z; As[c+3][r] = v.w;
        }
        #pragma unroll
        for (int l = 0; l < 2; l++) {
            int idx = tid + l * 256;
            int r = idx >> 5;
            int c = (idx & 31) * 4;
            *(float4*)&Ws[r][c] = *(const float4*)(W + (size_t)(k0 + r) * 512 + n0 + c);
        }
        __syncthreads();

        #pragma unroll
        for (int kk = 0; kk < 16; kk++) {
            // a: m-pairs for free via 16B reinterpret of k-major As
            ulonglong2 a01 = *(ulonglong2*)&As[kk][ty * 4];
            ulonglong2 a23 = *(ulonglong2*)&As[kk][ty * 4 + 64];
            u64 ap[4] = {a01.x, a01.y, a23.x, a23.y};
            float4 tb0 = *(float4*)&Ws[kk][tx * 4];
            float4 tb1 = *(float4*)&Ws[kk][tx * 4 + 64];
            u64 bp[8] = {pk2(tb0.x,tb0.x), pk2(tb0.y,tb0.y),
                         pk2(tb0.z,tb0.z), pk2(tb0.w,tb0.w),
                         pk2(tb1.x,tb1.x), pk2(tb1.y,tb1.y),
                         pk2(tb1.z,tb1.z), pk2(tb1.w,tb1.w)};
            #pragma unroll
            for (int p = 0; p < 4; p++)
                #pragma unroll
                for (int j = 0; j < 8; j++)
                    ffma2(acc2[p][j], ap[p], bp[j]);
        }
        __syncthreads();
    }

    float4 bv0 = *(const float4*)(bias + n0 + tx * 4);
    float4 bv1 = *(const float4*)(bias + n0 + tx * 4 + 64);
    const float bb[8] = {bv0.x, bv0.y, bv0.z, bv0.w, bv1.x, bv1.y, bv1.z, bv1.w};
    const int rowbase[4] = {ty*4, ty*4 + 2, 64 + ty*4, 64 + ty*4 + 2};
    #pragma unroll
    for (int p = 0; p < 4; p++) {
        float rlo[8], rhi[8];
        #pragma unroll
        for (int j = 0; j < 8; j++) {
            float2 t = upk(acc2[p][j]);
            rlo[j] = t.x + bb[j]; rhi[j] = t.y + bb[j];
        }
        size_t rl = (size_t)(m0 + rowbase[p]) * 512 + n0 + tx * 4;
        size_t rh = rl + 512;
        *(float4*)(C + rl)      = make_float4(rlo[0], rlo[1], rlo[2], rlo[3]);
        *(float4*)(C + rl + 64) = make_float4(rlo[4], rlo[5], rlo[6], rlo[7]);
        *(float4*)(C + rh)      = make_float4(rhi[0], rhi[1], rhi[2], rhi[3]);
        *(float4*)(C + rh + 64) = make_float4(rhi[4], rhi[5], rhi[6], rhi[7]);
    }
}

struct Proj5 {
    const float* A[5];
    const float* W[5];
    const float* bias[5];
    float*       C[5];
};

__global__ __launch_bounds__(256, 2) void proj5_kernel(Proj5 p)
{
    __shared__ float As[16][132];
    __shared__ float Ws[16][132];
    const int z = blockIdx.z;
    gemm_nn_core(p.A[z], p.W[z], p.bias[z], p.C[z], As, Ws);
}

__global__ __launch_bounds__(256, 2) void dense_kernel(
    const float* __restrict__ A, const float* __restrict__ W,
    const float* __restrict__ bias, float* __restrict__ C)
{
    __shared__ float As[16][132];
    __shared__ float Ws[16][132];
    gemm_nn_core(A, W, bias, C, As, Ws);
}

// =================================================================
// m kernel: per batch  m = sigmoid( (QP @ KP^T) / sqrt(512) )
// NT GEMM 128x128, BK=16, 8x8 micro, FFMA2, fused sigmoid
// =================================================================
__global__ __launch_bounds__(256, 2) void m_kernel(
    const float* __restrict__ QP, const float* __restrict__ KP,
    float* __restrict__ Mout)
{
    const int bz = blockIdx.z;
    const float* A  = QP + (size_t)bz * L_ * D_;
    const float* Bp = KP + (size_t)bz * L_ * D_;
    float* C = Mout + (size_t)bz * L_ * L_;

    __shared__ float As[16][132];
    __shared__ float Bs[16][132];
    const int tid = threadIdx.x;
    const int tx = tid & 15, ty = tid >> 4;
    const int m0 = blockIdx.y * 128, n0 = blockIdx.x * 128;

    u64 acc2[4][8] = {};

    for (int k0 = 0; k0 < 512; k0 += 16) {
        #pragma unroll
        for (int l = 0; l < 2; l++) {
            int idx = tid + l * 256;
            int r = idx & 127;
            int c = (idx >> 7) * 4;
            float4 v = *(const float4*)(A + (size_t)(m0 + r) * 512 + k0 + c);
            As[c+0][r] = v.x; As[c+1][r] = v.y;
            As[c+2][r] = v.z; As[c+3][r] = v.w;
            float4 w = *(const float4*)(Bp + (size_t)(n0 + r) * 512 + k0 + c);
            Bs[c+0][r] = w.x; Bs[c+1][r] = w.y;
            Bs[c+2][r] = w.z; Bs[c+3][r] = w.w;
        }
        __syncthreads();

        #pragma unroll
        for (int kk = 0; kk < 16; kk++) {
            ulonglong2 a01 = *(ulonglong2*)&As[kk][ty * 4];
            ulonglong2 a23 = *(ulonglong2*)&As[kk][ty * 4 + 64];
            u64 ap[4] = {a01.x, a01.y, a23.x, a23.y};
            float4 tb0 = *(float4*)&Bs[kk][tx * 4];
            float4 tb1 = *(float4*)&Bs[kk][tx * 4 + 64];
            u64 bp[8] = {pk2(tb0.x,tb0.x), pk2(tb0.y,tb0.y),
                         pk2(tb0.z,tb0.z), pk2(tb0.w,tb0.w),
                         pk2(tb1.x,tb1.x), pk2(tb1.y,tb1.y),
                         pk2(tb1.z,tb1.z), pk2(tb1.w,tb1.w)};
            #pragma unroll
            for (int p = 0; p < 4; p++)
                #pragma unroll
                for (int j = 0; j < 8; j++)
                    ffma2(acc2[p][j], ap[p], bp[j]);
        }
        __syncthreads();
    }

    const float sc = 0.04419417382415922f;   // 1/sqrt(512)
    const int rowbase[4] = {ty*4, ty*4 + 2, 64 + ty*4, 64 + ty*4 + 2};
    #pragma unroll
    for (int p = 0; p < 4; p++) {
        float rlo[8], rhi[8];
        #pragma unroll
        for (int j = 0; j < 8; j++) {
            float2 t = upk(acc2[p][j]);
            rlo[j] = 1.0f / (1.0f + __expf(-t.x * sc));
            rhi[j] = 1.0f / (1.0f + __expf(-t.y * sc));
        }
        size_t rl = (size_t)(m0 + rowbase[p]) * L_ + n0 + tx * 4;
        size_t rh = rl + L_;
        *(float4*)(C + rl)      = make_float4(rlo[0], rlo[1], rlo[2], rlo[3]);
        *(float4*)(C + rl + 64) = make_float4(rlo[4], rlo[5], rlo[6], rlo[7]);
        *(float4*)(C + rh)      = make_float4(rhi[0], rhi[1], rhi[2], rhi[3]);
        *(float4*)(C + rh + 64) = make_float4(rhi[4], rhi[5], rhi[6], rhi[7]);
    }
}

// =================================================================
// gate kernel
// =================================================================
__global__ __launch_bounds__(256) void gate_kernel(
    const float* __restrict__ query, const float* __restrict__ gw,
    const float* __restrict__ gb, float* __restrict__ g)
{
    const int row  = blockIdx.x * 8 + (threadIdx.x >> 5);
    const int lane = threadIdx.x & 31;
    const float* q = query + (size_t)row * D_;
    float s = 0.f;
    #pragma unroll
    for (int k = lane; k < D_; k += 32) s += q[k] * gw[k];
    #pragma unroll
    for (int o = 16; o; o >>= 1) s += __shfl_xor_sync(0xffffffffu, s, o);
    if (lane == 0) g[row] = 1.0f / (1.0f + __expf(-(s + gb[0])));
}

// =================================================================
// Fused attention kernel: one block = (b, h, 32 query rows), 512 thr.
// S: full 32x1024 scores in smem; two softmaxes + calibration fused.
// Phase1: 2q x 8k micro, FFMA2 (k-paired). Phase3: k-split halves,
// FFMA2 (d-paired), partial-sum combine through retired QT region.
// =================================================================
#define S_STRIDE 1032
#define QT_OFF   (32 * S_STRIDE)              // 33024
#define KT_OFF   (QT_OFF + 64 * 36)           // 35328
#define SMEM_FLOATS (KT_OFF + 64 * 260)       // 51968
#define ATTN_SMEM_BYTES (SMEM_FLOATS * 4)     // 207872

__global__ __launch_bounds__(512) void attn_kernel(
    const float* __restrict__ Q, const float* __restrict__ Kg,
    const float* __restrict__ Vg, const float* __restrict__ Mg,
    const float* __restrict__ gate, float* __restrict__ AV)
{
    extern __shared__ float sm[];
    float* S  = sm;              // [32][1032]
    float* QT = sm + QT_OFF;     // [64][36]  Q^T [d][q]; later reduce scratch
    float* KT = sm + KT_OFF;     // [64][260] K^T [d][k256]; later V [128][68]
    __shared__ float rowInv[32];

    const int tid = threadIdx.x;
    const int b = blockIdx.z, h = blockIdx.y, q0 = blockIdx.x * 32;

    const float* Qb = Q  + ((size_t)(b * L_ + q0)) * D_ + h * DK_;
    const float* Kb = Kg + (size_t)b * L_ * D_ + h * DK_;
    const float* Vb = Vg + (size_t)b * L_ * D_ + h * DK_;
    const float* Mb = Mg + (size_t)b * L_ * L_ + (size_t)q0 * L_;

    // ---- load Q tile transposed: QT[d][q] (512 float4, one pass) ----
    {
        int r = tid & 31;
        int c = (tid >> 5) << 2;
        float4 v = *(const float4*)(Qb + (size_t)r * D_ + c);
        QT[(c+0)*36 + r] = v.x; QT[(c+1)*36 + r] = v.y;
        QT[(c+2)*36 + r] = v.z; QT[(c+3)*36 + r] = v.w;
    }

    // ---- phase 1: S = (Q K^T) * 1/sqrt(64), k-chunks of 256 ----
    {
        const int tx  = tid & 31;             // k micro-group (8 k each)
        const int tyq = tid >> 5;             // q micro-group (2 q each, 16 groups)
        for (int k0 = 0; k0 < L_; k0 += 256) {
            #pragma unroll
            for (int l = 0; l < 8; l++) {
                int idx = tid + l * 512;
                int r = idx & 255;
                int c = (idx >> 8) << 2;
                float4 v = *(const float4*)(Kb + (size_t)(k0 + r) * D_ + c);
                KT[(c+0)*260 + r] = v.x; KT[(c+1)*260 + r] = v.y;
                KT[(c+2)*260 + r] = v.z; KT[(c+3)*260 + r] = v.w;
            }
            __syncthreads();

            u64 acc2[2][4] = {};              // [q][k-pair]
            #pragma unroll 8
            for (int d = 0; d < 64; d++) {
                float2 aa = *(float2*)(QT + d * 36 + tyq * 2);
                u64 a0 = pk2(aa.x, aa.x);
                u64 a1 = pk2(aa.y, aa.y);
                ulonglong2 b0 = *(ulonglong2*)(KT + d * 260 + tx * 4);
                ulonglong2 b1 = *(ulonglong2*)(KT + d * 260 + 128 + tx * 4);
                ffma2(acc2[0][0], a0, b0.x); ffma2(acc2[0][1], a0, b0.y);
                ffma2(acc2[0][2], a0, b1.x); ffma2(acc2[0][3], a0, b1.y);
                ffma2(acc2[1][0], a1, b0.x); ffma2(acc2[1][1], a1, b0.y);
                ffma2(acc2[1][2], a1, b1.x); ffma2(acc2[1][3], a1, b1.y);
            }
            #pragma unroll
            for (int i = 0; i < 2; i++) {
                float* Srow = S + (tyq * 2 + i) * S_STRIDE + k0;
                float2 p0 = upk(acc2[i][0]), p1 = upk(acc2[i][1]);
                float2 p2 = upk(acc2[i][2]), p3 = upk(acc2[i][3]);
                *(float4*)(Srow + tx * 4) =
                    make_float4(p0.x*0.125f, p0.y*0.125f, p1.x*0.125f, p1.y*0.125f);
                *(float4*)(Srow + 128 + tx * 4) =
                    make_float4(p2.x*0.125f, p2.y*0.125f, p3.x*0.125f, p3.y*0.125f);
            }
            __syncthreads();
        }
    }

    // ---- phase 2: softmax -> calibrate with m,g -> second softmax ----
    {
        const int warp = tid >> 5, lane = tid & 31;
        #pragma unroll
        for (int rr = 0; rr < 2; rr++) {
            const int r = warp * 2 + rr;
            float4* Srow4 = (float4*)(S + r * S_STRIDE);

            float mx = -1e30f;
            for (int i = lane; i < 256; i += 32) {
                float4 v = Srow4[i];
                mx = fmaxf(mx, fmaxf(fmaxf(v.x, v.y), fmaxf(v.z, v.w)));
            }
            #pragma unroll
            for (int o = 16; o; o >>= 1) mx = fmaxf(mx, __shfl_xor_sync(0xffffffffu, mx, o));

            float sum = 0.f;
            for (int i = lane; i < 256; i += 32) {
                float4 v = Srow4[i];
                v.x = __expf(v.x - mx); v.y = __expf(v.y - mx);
                v.z = __expf(v.z - mx); v.w = __expf(v.w - mx);
                Srow4[i] = v;
                sum += v.x + v.y + v.z + v.w;
            }
            #pragma unroll
            for (int o = 16; o; o >>= 1) sum += __shfl_xor_sync(0xffffffffu, sum, o);
            const float inv = 1.0f / sum;

            const float gq = gate[b * L_ + q0 + r];
            const float gq1 = 1.0f - gq;
            const float4* mrow4 = (const float4*)(Mb + (size_t)r * L_);
            float cmax = -1e30f;
            for (int i = lane; i < 256; i += 32) {
                float4 v = Srow4[i];
                float4 mm = mrow4[i];
                v.x *= inv * (gq + gq1 * __expf(1.0f - mm.x));
                v.y *= inv * (gq + gq1 * __expf(1.0f - mm.y));
                v.z *= inv * (gq + gq1 * __expf(1.0f - mm.z));
                v.w *= inv * (gq + gq1 * __expf(1.0f - mm.w));
                Srow4[i] = v;
                cmax = fmaxf(cmax, fmaxf(fmaxf(v.x, v.y), fmaxf(v.z, v.w)));
            }
            #pragma unroll
            for (int o = 16; o; o >>= 1) cmax = fmaxf(cmax, __shfl_xor_sync(0xffffffffu, cmax, o));

            float s2 = 0.f;
            for (int i = lane; i < 256; i += 32) {
                float4 v = Srow4[i];
                v.x = __expf(v.x - cmax); v.y = __expf(v.y - cmax);
                v.z = __expf(v.z - cmax); v.w = __expf(v.w - cmax);
                Srow4[i] = v;
                s2 += v.x + v.y + v.z + v.w;
            }
            #pragma unroll
            for (int o = 16; o; o >>= 1) s2 += __shfl_xor_sync(0xffffffffu, s2, o);
            if (lane == 0) rowInv[r] = 1.0f / s2;
        }
    }
    __syncthreads();

    // ---- phase 3: O = softmax2(P) @ V, k-split across two halves ----
    {
        const int tx  = tid & 15;             // d micro (4 d)
        const int tyq = (tid >> 4) & 15;      // q micro (2 q)
        const int kh  = tid >> 8;             // k-half 0/1
        u64 acc2[2][2] = {};                  // [q][d-pair]
        const float* S0 = S + (tyq * 2 + 0) * S_STRIDE;
        const float* S1 = S + (tyq * 2 + 1) * S_STRIDE;

        for (int k0 = 0; k0 < L_; k0 += 128) {
            #pragma unroll
            for (int l = 0; l < 4; l++) {
                int idx = tid + l * 512;      // V tile [128][68]
                int r = idx >> 4, c = (idx & 15) << 2;
                *(float4*)(KT + r * 68 + c) = *(const float4*)(Vb + (size_t)(k0 + r) * D_ + c);
            }
            __syncthreads();

            #pragma unroll 4
            for (int k4 = 0; k4 < 16; k4++) {
                const int kbase = kh * 64 + k4 * 4;
                float4 s0 = *(const float4*)(S0 + k0 + kbase);
                float4 s1 = *(const float4*)(S1 + k0 + kbase);
                float sa0[4] = {s0.x, s0.y, s0.z, s0.w};
                float sa1[4] = {s1.x, s1.y, s1.z, s1.w};
                #pragma unroll
                for (int j = 0; j < 4; j++) {
                    u64 p0 = pk2(sa0[j], sa0[j]);
                    u64 p1 = pk2(sa1[j], sa1[j]);
                    ulonglong2 vv = *(ulonglong2*)(KT + (kbase + j) * 68 + tx * 4);
                    ffma2(acc2[0][0], p0, vv.x); ffma2(acc2[0][1], p0, vv.y);
                    ffma2(acc2[1][0], p1, vv.x); ffma2(acc2[1][1], p1, vv.y);
                }
            }
            __syncthreads();
        }

        // combine k-halves through retired QT region (2048 floats needed)
        float* red = QT;
        const int slot = (tid & 255) * 8;
        if (kh == 1) {
            float2 t;
            t = upk(acc2[0][0]); red[slot+0] = t.x; red[slot+1] = t.y;
            t = upk(acc2[0][1]); red[slot+2] = t.x; red[slot+3] = t.y;
            t = upk(acc2[1][0]); red[slot+4] = t.x; red[slot+5] = t.y;
            t = upk(acc2[1][1]); red[slot+6] = t.x; red[slot+7] = t.y;
        }
        __syncthreads();
        if (kh == 0) {
            #pragma unroll
            for (int i = 0; i < 2; i++) {
                int r = tyq * 2 + i;
                float sc = rowInv[r];
                float2 p0 = upk(acc2[i][0]);
                float2 p1 = upk(acc2[i][1]);
                float4 o;
                o.x = (p0.x + red[slot + i*4 + 0]) * sc;
                o.y = (p0.y + red[slot + i*4 + 1]) * sc;
                o.z = (p1.x + red[slot + i*4 + 2]) * sc;
                o.w = (p1.y + red[slot + i*4 + 3]) * sc;
                *(float4*)(AV + ((size_t)(b * L_ + q0 + r)) * D_ + h * DK_ + tx * 4) = o;
            }
        }
    }
}

// =================================================================
// launcher
// =================================================================
extern "C" void kernel_launch(void* const* d_in, const int* in_sizes, int n_in,
                              void* d_out, int out_size)
{
    const float* query   = (const float*)d_in[0];
    const float* key     = (const float*)d_in[1];
    const float* value   = (const float*)d_in[2];
    const float* wq_w    = (const float*)d_in[3];
    const float* wq_b    = (const float*)d_in[4];
    const float* wk_w    = (const float*)d_in[5];
    const float* wk_b    = (const float*)d_in[6];
    const float* wv_w    = (const float*)d_in[7];
    const float* wv_b    = (const float*)d_in[8];
    const float* dense_w = (const float*)d_in[9];
    const float* dense_b = (const float*)d_in[10];
    const float* gate_w  = (const float*)d_in[11];
    const float* gate_b  = (const float*)d_in[12];
    const float* mp_wq_w = (const float*)d_in[13];
    const float* mp_wq_b = (const float*)d_in[14];
    const float* mp_wk_w = (const float*)d_in[15];
    const float* mp_wk_b = (const float*)d_in[16];

    float* out  = (float*)d_out;                    // (B, L, D)
    float* mout = out + (size_t)B_ * L_ * D_;       // (B, L, L)

    float *Qd, *Kd, *Vd, *QPd, *KPd, *AVd, *gd;
    cudaGetSymbolAddress((void**)&Qd,  g_Q);
    cudaGetSymbolAddress((void**)&Kd,  g_K);
    cudaGetSymbolAddress((void**)&Vd,  g_V);
    cudaGetSymbolAddress((void**)&QPd, g_QP);
    cudaGetSymbolAddress((void**)&KPd, g_KP);
    cudaGetSymbolAddress((void**)&AVd, g_AV);
    cudaGetSymbolAddress((void**)&gd,  g_g);

    Proj5 p;
    p.A[0] = query; p.W[0] = wq_w;    p.bias[0] = wq_b;    p.C[0] = Qd;
    p.A[1] = key;   p.W[1] = wk_w;    p.bias[1] = wk_b;    p.C[1] = Kd;
    p.A[2] = value; p.W[2] = wv_w;    p.bias[2] = wv_b;    p.C[2] = Vd;
    p.A[3] = query; p.W[3] = mp_wq_w; p.bias[3] = mp_wq_b; p.C[3] = QPd;
    p.A[4] = key;   p.W[4] = mp_wk_w; p.bias[4] = mp_wk_b; p.C[4] = KPd;

    proj5_kernel<<<dim3(D_ / 128, (B_ * L_) / 128, 5), 256>>>(p);

    gate_kernel<<<(B_ * L_) / 8, 256>>>(query, gate_w, gate_b, gd);

    m_kernel<<<dim3(L_ / 128, L_ / 128, B_), 256>>>(QPd, KPd, mout);

    cudaFuncSetAttribute(attn_kernel,
                         cudaFuncAttributeMaxDynamicSharedMemorySize,
                         ATTN_SMEM_BYTES);
    attn_kernel<<<dim3(L_ / 32, H_, B_), 512, ATTN_SMEM_BYTES>>>(
        Qd, Kd, Vd, mout, gd, AVd);

    dense_kernel<<<dim3(D_ / 128, (B_ * L_) / 128), 256>>>(AVd, dense_w, dense_b, out);
}

// round 13
// speedup vs baseline: 1.1090x; 1.1090x over previous
#include <cuda_runtime.h>

#define B_  4
#define L_  1024
#define D_  512
#define H_  8
#define DK_ 64

// ---------------- scratch (no allocations allowed) ----------------
__device__ float g_Q [B_*L_*D_];
__device__ float g_K [B_*L_*D_];
__device__ float g_V [B_*L_*D_];
__device__ float g_QP[B_*L_*D_];
__device__ float g_KP[B_*L_*D_];
__device__ float g_AV[B_*L_*D_];
__device__ float g_g [B_*L_];

// =================================================================
// Core NN SGEMM tile: C[M,N] = A[M,512] @ W[512,N] + bias
// 128x128 tile, BK=16, 256 threads, 8x8 micro-tile (scalar FFMA).
// =================================================================
__device__ __forceinline__ void gemm_nn_core(
    const float* __restrict__ A, const float* __restrict__ W,
    const float* __restrict__ bias, float* __restrict__ C,
    float As[16][132], float Ws[16][132])
{
    const int tid = threadIdx.x;
    const int tx = tid & 15;          // n micro-group
    const int ty = tid >> 4;          // m micro-group
    const int m0 = blockIdx.y * 128, n0 = blockIdx.x * 128;

    float acc[8][8] = {};

    for (int k0 = 0; k0 < 512; k0 += 16) {
        #pragma unroll
        for (int l = 0; l < 2; l++) {
            int idx = tid + l * 256;
            int r = idx & 127;
            int c = (idx >> 7) * 4;
            float4 v = *(const float4*)(A + (size_t)(m0 + r) * 512 + k0 + c);
            As[c+0][r] = v.x; As[c+1][r] = v.y;
            As[c+2][r] = v.z; As[c+3][r] = v.w;
        }
        #pragma unroll
        for (int l = 0; l < 2; l++) {
            int idx = tid + l * 256;
            int r = idx >> 5;
            int c = (idx & 31) * 4;
            *(float4*)&Ws[r][c] = *(const float4*)(W + (size_t)(k0 + r) * 512 + n0 + c);
        }
        __syncthreads();

        #pragma unroll
        for (int kk = 0; kk < 16; kk++) {
            float a_[8], b_[8];
            float4 t;
            t = *(float4*)&As[kk][ty * 4];      a_[0]=t.x; a_[1]=t.y; a_[2]=t.z; a_[3]=t.w;
            t = *(float4*)&As[kk][ty * 4 + 64]; a_[4]=t.x; a_[5]=t.y; a_[6]=t.z; a_[7]=t.w;
            t = *(float4*)&Ws[kk][tx * 4];      b_[0]=t.x; b_[1]=t.y; b_[2]=t.z; b_[3]=t.w;
            t = *(float4*)&Ws[kk][tx * 4 + 64]; b_[4]=t.x; b_[5]=t.y; b_[6]=t.z; b_[7]=t.w;
            #pragma unroll
            for (int i = 0; i < 8; i++)
                #pragma unroll
                for (int j = 0; j < 8; j++)
                    acc[i][j] += a_[i] * b_[j];
        }
        __syncthreads();
    }

    float4 bv0 = *(const float4*)(bias + n0 + tx * 4);
    float4 bv1 = *(const float4*)(bias + n0 + tx * 4 + 64);
    #pragma unroll
    for (int i = 0; i < 8; i++) {
        int row = m0 + ((i < 4) ? (ty * 4 + i) : (64 + ty * 4 + i - 4));
        float4 o0 = make_float4(acc[i][0] + bv0.x, acc[i][1] + bv0.y,
                                acc[i][2] + bv0.z, acc[i][3] + bv0.w);
        float4 o1 = make_float4(acc[i][4] + bv1.x, acc[i][5] + bv1.y,
                                acc[i][6] + bv1.z, acc[i][7] + bv1.w);
        *(float4*)(C + (size_t)row * 512 + n0 + tx * 4)      = o0;
        *(float4*)(C + (size_t)row * 512 + n0 + tx * 4 + 64) = o1;
    }
}

struct Proj5 {
    const float* A[5];
    const float* W[5];
    const float* bias[5];
    float*       C[5];
};

__global__ __launch_bounds__(256, 2) void proj5_kernel(Proj5 p)
{
    __shared__ float As[16][132];
    __shared__ float Ws[16][132];
    const int z = blockIdx.z;
    gemm_nn_core(p.A[z], p.W[z], p.bias[z], p.C[z], As, Ws);
}

__global__ __launch_bounds__(256, 2) void dense_kernel(
    const float* __restrict__ A, const float* __restrict__ W,
    const float* __restrict__ bias, float* __restrict__ C)
{
    __shared__ float As[16][132];
    __shared__ float Ws[16][132];
    gemm_nn_core(A, W, bias, C, As, Ws);
}

// =================================================================
// m kernel: per batch  m = sigmoid( (QP @ KP^T) / sqrt(512) )
// NT GEMM 128x128, BK=16, 8x8 micro, fused sigmoid -> d_out m region
// =================================================================
__global__ __launch_bounds__(256, 2) void m_kernel(
    const float* __restrict__ QP, const float* __restrict__ KP,
    float* __restrict__ Mout)
{
    const int bz = blockIdx.z;
    const float* A  = QP + (size_t)bz * L_ * D_;
    const float* Bp = KP + (size_t)bz * L_ * D_;
    float* C = Mout + (size_t)bz * L_ * L_;

    __shared__ float As[16][132];
    __shared__ float Bs[16][132];
    const int tid = threadIdx.x;
    const int tx = tid & 15, ty = tid >> 4;
    const int m0 = blockIdx.y * 128, n0 = blockIdx.x * 128;

    float acc[8][8] = {};

    for (int k0 = 0; k0 < 512; k0 += 16) {
        #pragma unroll
        for (int l = 0; l < 2; l++) {
            int idx = tid + l * 256;
            int r = idx & 127;
            int c = (idx >> 7) * 4;
            float4 v = *(const float4*)(A + (size_t)(m0 + r) * 512 + k0 + c);
            As[c+0][r] = v.x; As[c+1][r] = v.y;
            As[c+2][r] = v.z; As[c+3][r] = v.w;
            float4 w = *(const float4*)(Bp + (size_t)(n0 + r) * 512 + k0 + c);
            Bs[c+0][r] = w.x; Bs[c+1][r] = w.y;
            Bs[c+2][r] = w.z; Bs[c+3][r] = w.w;
        }
        __syncthreads();

        #pragma unroll
        for (int kk = 0; kk < 16; kk++) {
            float a_[8], b_[8];
            float4 t;
            t = *(float4*)&As[kk][ty * 4];      a_[0]=t.x; a_[1]=t.y; a_[2]=t.z; a_[3]=t.w;
            t = *(float4*)&As[kk][ty * 4 + 64]; a_[4]=t.x; a_[5]=t.y; a_[6]=t.z; a_[7]=t.w;
            t = *(float4*)&Bs[kk][tx * 4];      b_[0]=t.x; b_[1]=t.y; b_[2]=t.z; b_[3]=t.w;
            t = *(float4*)&Bs[kk][tx * 4 + 64]; b_[4]=t.x; b_[5]=t.y; b_[6]=t.z; b_[7]=t.w;
            #pragma unroll
            for (int i = 0; i < 8; i++)
                #pragma unroll
                for (int j = 0; j < 8; j++)
                    acc[i][j] += a_[i] * b_[j];
        }
        __syncthreads();
    }

    const float sc = 0.04419417382415922f;   // 1/sqrt(512)
    #pragma unroll
    for (int i = 0; i < 8; i++) {
        int row = m0 + ((i < 4) ? (ty * 4 + i) : (64 + ty * 4 + i - 4));
        float4 o0, o1;
        o0.x = 1.0f / (1.0f + __expf(-acc[i][0] * sc));
        o0.y = 1.0f / (1.0f + __expf(-acc[i][1] * sc));
        o0.z = 1.0f / (1.0f + __expf(-acc[i][2] * sc));
        o0.w = 1.0f / (1.0f + __expf(-acc[i][3] * sc));
        o1.x = 1.0f / (1.0f + __expf(-acc[i][4] * sc));
        o1.y = 1.0f / (1.0f + __expf(-acc[i][5] * sc));
        o1.z = 1.0f / (1.0f + __expf(-acc[i][6] * sc));
        o1.w = 1.0f / (1.0f + __expf(-acc[i][7] * sc));
        *(float4*)(C + (size_t)row * L_ + n0 + tx * 4)      = o0;
        *(float4*)(C + (size_t)row * L_ + n0 + tx * 4 + 64) = o1;
    }
}

// =================================================================
// gate kernel: g = sigmoid(query @ gate_w + gate_b), one warp per row
// =================================================================
__global__ __launch_bounds__(256) void gate_kernel(
    const float* __restrict__ query, const float* __restrict__ gw,
    const float* __restrict__ gb, float* __restrict__ g)
{
    const int row  = blockIdx.x * 8 + (threadIdx.x >> 5);
    const int lane = threadIdx.x & 31;
    const float* q = query + (size_t)row * D_;
    float s = 0.f;
    #pragma unroll
    for (int k = lane; k < D_; k += 32) s += q[k] * gw[k];
    #pragma unroll
    for (int o = 16; o; o >>= 1) s += __shfl_xor_sync(0xffffffffu, s, o);
    if (lane == 0) g[row] = 1.0f / (1.0f + __expf(-(s + gb[0])));
}

// =================================================================
// Fused attention kernel: one block = (b, h, 32 query rows), 256 thr.
// Phase1: 4q x 8k micro (QT warp-broadcast).   [FMA-bound]
// Phase2: fully vectorized double softmax + calibration.
// Phase3: 4q x 4d micro, 2-way k-split (S warp-broadcast, V reuse x4),
//         partials combined through retired QT region.  [FMA-bound]
// =================================================================
#define S_STRIDE 1032
#define QT_OFF   (32 * S_STRIDE)              // 33024
#define KT_OFF   (QT_OFF + 64 * 36)           // 35328
#define SMEM_FLOATS (KT_OFF + 64 * 260)       // 51968
#define ATTN_SMEM_BYTES (SMEM_FLOATS * 4)     // 207872

__global__ __launch_bounds__(256) void attn_kernel(
    const float* __restrict__ Q, const float* __restrict__ Kg,
    const float* __restrict__ Vg, const float* __restrict__ Mg,
    const float* __restrict__ gate, float* __restrict__ AV)
{
    extern __shared__ float sm[];
    float* S  = sm;              // [32][1032]
    float* QT = sm + QT_OFF;     // [64][36]  Q^T [d][q]; later reduce scratch
    float* KT = sm + KT_OFF;     // [64][260] K^T [d][k256]; later V [128][68]
    __shared__ float rowInv[32];

    const int tid = threadIdx.x;
    const int b = blockIdx.z, h = blockIdx.y, q0 = blockIdx.x * 32;

    const float* Qb = Q  + ((size_t)(b * L_ + q0)) * D_ + h * DK_;
    const float* Kb = Kg + (size_t)b * L_ * D_ + h * DK_;
    const float* Vb = Vg + (size_t)b * L_ * D_ + h * DK_;
    const float* Mb = Mg + (size_t)b * L_ * L_ + (size_t)q0 * L_;

    // ---- load Q tile transposed: QT[d][q], conflict-free STS ----
    #pragma unroll
    for (int l = 0; l < 2; l++) {
        int idx = tid + l * 256;              // 512 float4 : 32 rows x 16 chunks
        int r = idx & 31;
        int c = (idx >> 5) * 4;
        float4 v = *(const float4*)(Qb + (size_t)r * D_ + c);
        QT[(c+0)*36 + r] = v.x; QT[(c+1)*36 + r] = v.y;
        QT[(c+2)*36 + r] = v.z; QT[(c+3)*36 + r] = v.w;
    }

    // ---- phase 1: S = (Q K^T) * 1/sqrt(64), k-chunks of 256 ----
    {
        const int tx = tid & 31;              // k micro-group (8 k each)
        const int ty = tid >> 5;              // q micro-group (4 q each)
        for (int k0 = 0; k0 < L_; k0 += 256) {
            // K tile 256x64 -> KT[d][k]
            #pragma unroll
            for (int l = 0; l < 16; l++) {
                int idx = tid + l * 256;
                int r = idx & 255;
                int c = (idx >> 8) * 4;
                float4 v = *(const float4*)(Kb + (size_t)(k0 + r) * D_ + c);
                KT[(c+0)*260 + r] = v.x; KT[(c+1)*260 + r] = v.y;
                KT[(c+2)*260 + r] = v.z; KT[(c+3)*260 + r] = v.w;
            }
            __syncthreads();

            float acc[4][8] = {};
            #pragma unroll 8
            for (int d = 0; d < 64; d++) {
                float4 a4 = *(float4*)(QT + d * 36 + ty * 4);
                float4 b0 = *(float4*)(KT + d * 260 + tx * 4);
                float4 b1 = *(float4*)(KT + d * 260 + 128 + tx * 4);
                float a_[4] = {a4.x, a4.y, a4.z, a4.w};
                float b_[8] = {b0.x, b0.y, b0.z, b0.w, b1.x, b1.y, b1.z, b1.w};
                #pragma unroll
                for (int i = 0; i < 4; i++)
                    #pragma unroll
                    for (int j = 0; j < 8; j++)
                        acc[i][j] += a_[i] * b_[j];
            }
            #pragma unroll
            for (int i = 0; i < 4; i++) {
                float* Srow = S + (ty * 4 + i) * S_STRIDE + k0;
                float4 o0 = make_float4(acc[i][0]*0.125f, acc[i][1]*0.125f,
                                        acc[i][2]*0.125f, acc[i][3]*0.125f);
                float4 o1 = make_float4(acc[i][4]*0.125f, acc[i][5]*0.125f,
                                        acc[i][6]*0.125f, acc[i][7]*0.125f);
                *(float4*)(Srow + tx * 4)       = o0;
                *(float4*)(Srow + 128 + tx * 4) = o1;
            }
            __syncthreads();
        }
    }

    // ---- phase 2: softmax -> calibrate with m,g -> second softmax ----
    {
        const int warp = tid >> 5, lane = tid & 31;
        #pragma unroll
        for (int rr = 0; rr < 4; rr++) {
            const int r = warp * 4 + rr;
            float4* Srow4 = (float4*)(S + r * S_STRIDE);

            float mx = -1e30f;
            for (int i = lane; i < 256; i += 32) {
                float4 v = Srow4[i];
                mx = fmaxf(mx, fmaxf(fmaxf(v.x, v.y), fmaxf(v.z, v.w)));
            }
            #pragma unroll
            for (int o = 16; o; o >>= 1) mx = fmaxf(mx, __shfl_xor_sync(0xffffffffu, mx, o));

            float sum = 0.f;
            for (int i = lane; i < 256; i += 32) {
                float4 v = Srow4[i];
                v.x = __expf(v.x - mx); v.y = __expf(v.y - mx);
                v.z = __expf(v.z - mx); v.w = __expf(v.w - mx);
                Srow4[i] = v;
                sum += v.x + v.y + v.z + v.w;
            }
            #pragma unroll
            for (int o = 16; o; o >>= 1) sum += __shfl_xor_sync(0xffffffffu, sum, o);
            const float inv = 1.0f / sum;

            const float gq = gate[b * L_ + q0 + r];
            const float gq1 = 1.0f - gq;
            const float4* mrow4 = (const float4*)(Mb + (size_t)r * L_);
            float cmax = -1e30f;
            for (int i = lane; i < 256; i += 32) {
                float4 v = Srow4[i];
                float4 mm = mrow4[i];
                v.x *= inv * (gq + gq1 * __expf(1.0f - mm.x));
                v.y *= inv * (gq + gq1 * __expf(1.0f - mm.y));
                v.z *= inv * (gq + gq1 * __expf(1.0f - mm.z));
                v.w *= inv * (gq + gq1 * __expf(1.0f - mm.w));
                Srow4[i] = v;
                cmax = fmaxf(cmax, fmaxf(fmaxf(v.x, v.y), fmaxf(v.z, v.w)));
            }
            #pragma unroll
            for (int o = 16; o; o >>= 1) cmax = fmaxf(cmax, __shfl_xor_sync(0xffffffffu, cmax, o));

            float s2 = 0.f;
            for (int i = lane; i < 256; i += 32) {
                float4 v = Srow4[i];
                v.x = __expf(v.x - cmax); v.y = __expf(v.y - cmax);
                v.z = __expf(v.z - cmax); v.w = __expf(v.w - cmax);
                Srow4[i] = v;
                s2 += v.x + v.y + v.z + v.w;
            }
            #pragma unroll
            for (int o = 16; o; o >>= 1) s2 += __shfl_xor_sync(0xffffffffu, s2, o);
            if (lane == 0) rowInv[r] = 1.0f / s2;
        }
    }
    __syncthreads();

    // ---- phase 3: O = softmax2(P) @ V ----
    // 4q x 4d micro, 2-way k-split. Warp = (16 d-groups x 2 k-splits),
    // q uniform per warp -> S float4 loads broadcast (1 wf);
    // V loads conflict-free. Partials combined via QT scratch.
    {
        const int gd = tid & 15;              // d quad: cols gd*4..+3
        const int gk = (tid >> 4) & 1;        // k half within 8-k group
        const int gq = tid >> 5;              // q quad: rows gq*4..+3

        float acc[4][4] = {};

        for (int k0 = 0; k0 < L_; k0 += 128) {
            #pragma unroll
            for (int l = 0; l < 8; l++) {
                int idx = tid + l * 256;      // V tile [128][68]
                int r = idx >> 4, c = (idx & 15) << 2;
                *(float4*)(KT + r * 68 + c) = *(const float4*)(Vb + (size_t)(k0 + r) * D_ + c);
            }
            __syncthreads();

            #pragma unroll 4
            for (int t = 0; t < 16; t++) {
                const int kb = t * 8 + gk * 4;      // local k base (0..124)
                float4 s0 = *(const float4*)(S + (gq*4 + 0) * S_STRIDE + k0 + kb);
                float4 s1 = *(const float4*)(S + (gq*4 + 1) * S_STRIDE + k0 + kb);
                float4 s2 = *(const float4*)(S + (gq*4 + 2) * S_STRIDE + k0 + kb);
                float4 s3 = *(const float4*)(S + (gq*4 + 3) * S_STRIDE + k0 + kb);
                float sa0[4] = {s0.x, s0.y, s0.z, s0.w};
                float sa1[4] = {s1.x, s1.y, s1.z, s1.w};
                float sa2[4] = {s2.x, s2.y, s2.z, s2.w};
                float sa3[4] = {s3.x, s3.y, s3.z, s3.w};
                #pragma unroll
                for (int j = 0; j < 4; j++) {
                    float4 v = *(float4*)(KT + (kb + j) * 68 + gd * 4);
                    acc[0][0] += sa0[j] * v.x; acc[0][1] += sa0[j] * v.y;
                    acc[0][2] += sa0[j] * v.z; acc[0][3] += sa0[j] * v.w;
                    acc[1][0] += sa1[j] * v.x; acc[1][1] += sa1[j] * v.y;
                    acc[1][2] += sa1[j] * v.z; acc[1][3] += sa1[j] * v.w;
                    acc[2][0] += sa2[j] * v.x; acc[2][1] += sa2[j] * v.y;
                    acc[2][2] += sa2[j] * v.z; acc[2][3] += sa2[j] * v.w;
                    acc[3][0] += sa3[j] * v.x; acc[3][1] += sa3[j] * v.y;
                    acc[3][2] += sa3[j] * v.z; acc[3][3] += sa3[j] * v.w;
                }
            }
            __syncthreads();
        }

        // combine the two k-halves through retired QT region (stride-17 pad)
        const int p = gq * 16 + gd;           // 0..127
        float* red = QT + p * 17;
        if (gk == 1) {
            #pragma unroll
            for (int qi = 0; qi < 4; qi++)
                #pragma unroll
                for (int j = 0; j < 4; j++)
                    red[qi * 4 + j] = acc[qi][j];
        }
        __syncthreads();
        if (gk == 0) {
            #pragma unroll
            for (int qi = 0; qi < 4; qi++) {
                const int r = gq * 4 + qi;
                const float sc = rowInv[r];
                float4 o;
                o.x = (acc[qi][0] + red[qi*4 + 0]) * sc;
                o.y = (acc[qi][1] + red[qi*4 + 1]) * sc;
                o.z = (acc[qi][2] + red[qi*4 + 2]) * sc;
                o.w = (acc[qi][3] + red[qi*4 + 3]) * sc;
                *(float4*)(AV + ((size_t)(b * L_ + q0 + r)) * D_ + h * DK_ + gd * 4) = o;
            }
        }
    }
}

// =================================================================
// launcher
// =================================================================
extern "C" void kernel_launch(void* const* d_in, const int* in_sizes, int n_in,
                              void* d_out, int out_size)
{
    const float* query   = (const float*)d_in[0];
    const float* key     = (const float*)d_in[1];
    const float* value   = (const float*)d_in[2];
    const float* wq_w    = (const float*)d_in[3];
    const float* wq_b    = (const float*)d_in[4];
    const float* wk_w    = (const float*)d_in[5];
    const float* wk_b    = (const float*)d_in[6];
    const float* wv_w    = (const float*)d_in[7];
    const float* wv_b    = (const float*)d_in[8];
    const float* dense_w = (const float*)d_in[9];
    const float* dense_b = (const float*)d_in[10];
    const float* gate_w  = (const float*)d_in[11];
    const float* gate_b  = (const float*)d_in[12];
    const float* mp_wq_w = (const float*)d_in[13];
    const float* mp_wq_b = (const float*)d_in[14];
    const float* mp_wk_w = (const float*)d_in[15];
    const float* mp_wk_b = (const float*)d_in[16];

    float* out  = (float*)d_out;                    // (B, L, D)
    float* mout = out + (size_t)B_ * L_ * D_;       // (B, L, L)

    float *Qd, *Kd, *Vd, *QPd, *KPd, *AVd, *gd;
    cudaGetSymbolAddress((void**)&Qd,  g_Q);
    cudaGetSymbolAddress((void**)&Kd,  g_K);
    cudaGetSymbolAddress((void**)&Vd,  g_V);
    cudaGetSymbolAddress((void**)&QPd, g_QP);
    cudaGetSymbolAddress((void**)&KPd, g_KP);
    cudaGetSymbolAddress((void**)&AVd, g_AV);
    cudaGetSymbolAddress((void**)&gd,  g_g);

    Proj5 p;
    p.A[0] = query; p.W[0] = wq_w;    p.bias[0] = wq_b;    p.C[0] = Qd;
    p.A[1] = key;   p.W[1] = wk_w;    p.bias[1] = wk_b;    p.C[1] = Kd;
    p.A[2] = value; p.W[2] = wv_w;    p.bias[2] = wv_b;    p.C[2] = Vd;
    p.A[3] = query; p.W[3] = mp_wq_w; p.bias[3] = mp_wq_b; p.C[3] = QPd;
    p.A[4] = key;   p.W[4] = mp_wk_w; p.bias[4] = mp_wk_b; p.C[4] = KPd;

    proj5_kernel<<<dim3(D_ / 128, (B_ * L_) / 128, 5), 256>>>(p);

    gate_kernel<<<(B_ * L_) / 8, 256>>>(query, gate_w, gate_b, gd);

    m_kernel<<<dim3(L_ / 128, L_ / 128, B_), 256>>>(QPd, KPd, mout);

    cudaFuncSetAttribute(attn_kernel,
                         cudaFuncAttributeMaxDynamicSharedMemorySize,
                         ATTN_SMEM_BYTES);
    attn_kernel<<<dim3(L_ / 32, H_, B_), 256, ATTN_SMEM_BYTES>>>(
        Qd, Kd, Vd, mout, gd, AVd);

    dense_kernel<<<dim3(D_ / 128, (B_ * L_) / 128), 256>>>(AVd, dense_w, dense_b, out);
}